// round 12
// baseline (speedup 1.0000x reference)
#include <cuda_runtime.h>
#include <cuda_fp16.h>
#include <cstdint>
#include <math.h>

// ---------------- problem constants ----------------
#define NF     128
#define BATCH  4
#define TT     8
#define NPIX   1024
#define C1     384
#define C23    256
#define K1     (C1 * 9)       // 3456
#define PADPL  (34 * 34)

// pad sizes (halves)
#define P1P (BATCH * PADPL * C1)
#define P2P (BATCH * PADPL * C23)

// GEMM tiling: CTA 32x128x32, 8 warps = 2(k-split) x 4(n), warp tile 32x32, mma m16n8k16
#define BM 32
#define STAGES 4
#define A_BYTES (32 * 40 * 2)       // 2560 (32 m-rows, stride 40 halves: conflict-free)
#define B_BYTES (4096 * 2)          // 8192 (128 n x 32 k halves)
#define STG_B  (A_BYTES + B_BYTES)  // 10752
#define SMEM_DYN (STAGES * STG_B)   // 43008 B -> 4 CTAs/SM

// ---------------- persistent device scratch ----------------
__device__ __align__(256) __half g_pad1[2 * P1P];   // [par][b][y][x][384]: x1|x2|h1
__device__ __align__(256) __half g_pad2[2 * P2P];   // [par][b][y][x][256]: h1|h2
__device__ __align__(256) __half g_pad3[2 * P2P];   // [par][b][y][x][256]: h2|h3
__device__ __align__(256) float g_c1[BATCH * NF * NPIX];
__device__ __align__(256) float g_c2[BATCH * NF * NPIX];
__device__ __align__(256) float g_c3[BATCH * NF * NPIX];
__device__ __align__(256) __half g_wf1[K1 * 512];
__device__ __align__(256) __half g_wf2[C23 * 9 * 512];
__device__ __align__(256) __half g_wf3[C23 * 9 * 512];
__device__ float g_bp1[512];
__device__ float g_bp2[512];
__device__ float g_bp3[512];

__device__ __forceinline__ uint32_t smem_u32(const void* p) {
    uint32_t a;
    asm("{ .reg .u64 t; cvta.to.shared.u64 t, %1; cvt.u32.u64 %0, t; }" : "=r"(a) : "l"(p));
    return a;
}
#define CP_ASYNC16(dst, src) \
    asm volatile("cp.async.cg.shared.global [%0], [%1], 16;" :: "r"(dst), "l"(src))
#define CP_COMMIT() asm volatile("cp.async.commit_group;" ::: "memory")
#define CP_WAIT(n)  asm volatile("cp.async.wait_group %0;" :: "n"(n) : "memory")

__device__ __forceinline__ void ldmatrix4(uint32_t* a, uint32_t addr) {
    asm volatile("ldmatrix.sync.aligned.m8n8.x4.shared.b16 {%0,%1,%2,%3}, [%4];"
                 : "=r"(a[0]), "=r"(a[1]), "=r"(a[2]), "=r"(a[3]) : "r"(addr));
}
__device__ __forceinline__ void mma16(float* c, const uint32_t* a, uint32_t b0, uint32_t b1) {
    asm volatile(
        "mma.sync.aligned.m16n8k16.row.col.f32.f16.f16.f32 "
        "{%0,%1,%2,%3}, {%4,%5,%6,%7}, {%8,%9}, {%0,%1,%2,%3};"
        : "+f"(c[0]), "+f"(c[1]), "+f"(c[2]), "+f"(c[3])
        : "r"(a[0]), "r"(a[1]), "r"(a[2]), "r"(a[3]), "r"(b0), "r"(b1));
}

// ---------------- init: zero pads + c-states (1 launch) ----------------
__global__ void init_kernel() {
    long i = (long)blockIdx.x * 256 + threadIdx.x;
    long n;
    n = P1P;                 if (i < n) { ((uint32_t*)g_pad1)[i] = 0u; return; } i -= n;
    n = P2P;                 if (i < n) { ((uint32_t*)g_pad2)[i] = 0u; return; } i -= n;
    n = P2P;                 if (i < n) { ((uint32_t*)g_pad3)[i] = 0u; return; } i -= n;
    n = BATCH * NF * NPIX;
    if (i < n) { g_c1[i] = 0.0f; return; } i -= n;
    if (i < n) { g_c2[i] = 0.0f; return; } i -= n;
    if (i < n) { g_c3[i] = 0.0f; return; }
}
#define INIT_TOTAL ((long)P1P + 2L * P2P + 3L * BATCH * NF * NPIX)

// ---------------- weight prep: fp16 fragment-ordered gmem ----------------
// chunk = 32k x 128n' = 4096 halves: [ny4][ck][wn4][ks2][pair2][lane32][jj2][bsel2][h2]
__device__ __forceinline__ void wstore(const float* __restrict__ W, __half* __restrict__ out,
                                       int np, int k, int Cin, int NCH) {
    int K = Cin * 9;
    int ch = np >> 2, g = np & 3;
    int tap = k / Cin, ci = k - tap * Cin;
    __half v = __float2half_rn(W[(size_t)(g * 128 + ch) * K + ci * 9 + tap]);
    int ny = np >> 7, n_t = np & 127;
    int wn = n_t >> 5, nl = n_t & 31;
    int j = nl >> 3, rn = nl & 7, pair = j >> 1, jj = j & 1;
    int ck = k >> 5, kl = k & 31, ks = kl >> 4, rk = kl & 15;
    int bsel = rk >> 3, c = (rk & 7) >> 1, hh = rk & 1;
    int lane = rn * 4 + c;
    size_t off = (size_t)(ny * NCH + ck) * 4096 + wn * 1024 + ks * 512
               + pair * 256 + lane * 8 + jj * 4 + bsel * 2 + hh;
    out[off] = v;
}
__global__ void wprep_kernel(const float* __restrict__ W1, const float* __restrict__ b1,
                             const float* __restrict__ W2, const float* __restrict__ b2,
                             const float* __restrict__ W3, const float* __restrict__ b3) {
    int idx = blockIdx.x * 256 + threadIdx.x;
    if (idx < 512) {
        int src = (idx & 3) * 128 + (idx >> 2);
        g_bp1[idx] = b1[src]; g_bp2[idx] = b2[src]; g_bp3[idx] = b3[src];
    }
    if (idx >= K1 * 512) return;
    int np = idx & 511, k = idx >> 9;
    wstore(W1, g_wf1, np, k, C1, K1 / 32);
    if (k < C23 * 9) {
        wstore(W2, g_wf2, np, k, C23, C23 * 9 / 32);
        wstore(W3, g_wf3, np, k, C23, C23 * 9 / 32);
    }
}

// ---------------- per-step x pack: channel-last transpose (8 launches) ------
__global__ void pack_x_kernel(const float* __restrict__ x1, const float* __restrict__ x2,
                              int t, int par) {
    __shared__ __half tile[8][32][33];
    const int w = threadIdx.x >> 5, lane = threadIdx.x & 31;
    const int tl = blockIdx.x * 8 + w;
    const int b = tl >> 8, rest = tl & 255;
    const int cb = rest >> 5, pb = rest & 31;
    const int ch0 = cb * 32, pix0 = pb * 32;

    const float* src = (ch0 < 128) ? (x1 + ((size_t)(b * TT + t) * 128 + ch0) * NPIX)
                                   : (x2 + ((size_t)(b * TT + t) * 128 + ch0 - 128) * NPIX);
#pragma unroll
    for (int r = 0; r < 32; ++r)
        tile[w][r][lane] = __float2half_rn(src[(size_t)r * NPIX + pix0 + lane]);
    __syncwarp();

    __half* dst0 = g_pad1 + (size_t)par * P1P;
#pragma unroll
    for (int p = 0; p < 32; p += 2) {
        const int pp = p + (lane >> 4), ll = lane & 15;
        const int pix = pix0 + pp;
        const int py = (pix >> 5) + 1, px = (pix & 31) + 1;
        uint32_t v = ((uint32_t)__half_as_ushort(tile[w][2 * ll + 1][pp]) << 16)
                   | (uint32_t)__half_as_ushort(tile[w][2 * ll][pp]);
        __half* d = dst0 + ((size_t)((b * 34 + py) * 34 + px)) * C1 + ch0 + 2 * ll;
        *(uint32_t*)d = v;
    }
}

// ---------------- fused fp16 GEMM + LSTM kernel ----------------
// grid (128, 4), 256 threads (8 warps = 2 k-split x 4 n, warp tile 32x32).
template <int C, int LAYER>
__global__ void __launch_bounds__(256, 4)
gemm_lstm_kernel(const __half* __restrict__ Bf, const float* __restrict__ bp,
                 float* __restrict__ c_st, float* __restrict__ h_out, int par)
{
    constexpr int NCH = C * 9 / 32;
    extern __shared__ char sm[];
    const uint32_t sb = smem_u32(sm);

    const int tid = threadIdx.x, w = tid >> 5, lane = tid & 31;
    const int wn = w >> 1, wk = w & 1;
    const int m0 = blockIdx.x * BM, b = m0 >> 10, pix0 = m0 & 1023;
    const int ny = blockIdx.y;
    const __half* Bny = Bf + (size_t)ny * NCH * 4096;

    // A loader: threads 0..127 cover 32 pixels x 32 channels (16B each)
    const int pxA = (tid & 127) >> 2;
    const int chq = (tid & 3) << 3;
    const int pixL = pix0 + pxA;
    const int yL = pixL >> 5, xL = pixL & 31;

    const __half* padIn =
        (LAYER == 1) ? (g_pad1 + (size_t)par * P1P)
      : (LAYER == 2) ? (g_pad2 + (size_t)par * P2P)
                     : (g_pad3 + (size_t)par * P2P);

    // ldmatrix lane geometry: warp covers 32m x 16k (k-slice = wk)
    const int q = lane >> 3, r = lane & 7;
    const int arow = ((q & 1) * 8 + r) * 40 + wk * 16 + (q >> 1) * 8;

    float acc[2][4][4];
#pragma unroll
    for (int mt = 0; mt < 2; ++mt)
#pragma unroll
        for (int jn = 0; jn < 4; ++jn)
#pragma unroll
            for (int qq = 0; qq < 4; ++qq) acc[mt][jn][qq] = 0.0f;

    auto issue = [&](int ck, int s) {
        const uint32_t stA = sb + s * STG_B;
        const uint32_t stB = stA + A_BYTES;
        if (tid < 128) {
            const int kg = ck << 5;
            const int tap = kg / C;             // compile-time divisor
            const int ch0 = kg - tap * C;
            const int kh = tap / 3, kw = tap - kh * 3;
            const __half* srcA = padIn
                + ((size_t)((b * 34 + yL + kh) * 34 + xL + kw)) * C + ch0 + chq;
            CP_ASYNC16(stA + (pxA * 40 + chq) * 2, srcA);
        }
        const __half* srcB = Bny + ((size_t)ck << 12) + (tid << 3);
        CP_ASYNC16(stB + tid * 16, srcB);
        CP_ASYNC16(stB + 4096 + tid * 16, srcB + 2048);
        CP_COMMIT();
    };

#pragma unroll
    for (int s = 0; s < STAGES - 1; ++s) issue(s, s);

    int st = 0;
    for (int ck = 0; ck < NCH; ++ck) {
        CP_WAIT(STAGES - 2);
        __syncthreads();
        const int nx = ck + STAGES - 1;
        if (nx < NCH) {
            int sn = st + STAGES - 1; if (sn >= STAGES) sn -= STAGES;
            issue(nx, sn);
        }
        const uint32_t As = sb + st * STG_B;
        const uint32_t Bs = As + A_BYTES + (wn << 11);

        uint32_t af[2][4];
#pragma unroll
        for (int mt = 0; mt < 2; ++mt)
            ldmatrix4(af[mt], As + (arow + mt * 640) * 2);
#pragma unroll
        for (int pair = 0; pair < 2; ++pair) {
            uint4 bq;
            asm volatile("ld.shared.v4.b32 {%0,%1,%2,%3}, [%4];"
                         : "=r"(bq.x), "=r"(bq.y), "=r"(bq.z), "=r"(bq.w)
                         : "r"(Bs + (wk * 512 + pair * 256 + lane * 8) * 2));
#pragma unroll
            for (int mt = 0; mt < 2; ++mt) {
                mma16(acc[mt][pair * 2 + 0], af[mt], bq.x, bq.y);
                mma16(acc[mt][pair * 2 + 1], af[mt], bq.z, bq.w);
            }
        }
        if (++st == STAGES) st = 0;
    }

    // ---- cross-warp k-split reduction (wk=1 -> wk=0) via smem ----
    float* red = (float*)sm;
    __syncthreads();
    if (wk == 1) {
#pragma unroll
        for (int mt = 0; mt < 2; ++mt)
#pragma unroll
            for (int jn = 0; jn < 4; ++jn)
                *(float4*)&red[(((wn * 8 + mt * 4 + jn) * 32) + lane) * 4] =
                    make_float4(acc[mt][jn][0], acc[mt][jn][1], acc[mt][jn][2], acc[mt][jn][3]);
    }
    __syncthreads();
    if (wk == 0) {
#pragma unroll
        for (int mt = 0; mt < 2; ++mt)
#pragma unroll
            for (int jn = 0; jn < 4; ++jn) {
                float4 v = *(float4*)&red[(((wn * 8 + mt * 4 + jn) * 32) + lane) * 4];
                acc[mt][jn][0] += v.x; acc[mt][jn][1] += v.y;
                acc[mt][jn][2] += v.z; acc[mt][jn][3] += v.w;
            }

        // ---- fused LSTM epilogue + channel-last pad writes ----
        const int lane4 = lane & 3;
#pragma unroll
        for (int mt = 0; mt < 2; ++mt) {
#pragma unroll
            for (int jn = 0; jn < 4; ++jn) {
                const int nc = (ny << 7) + (wn << 5) + (jn << 3) + (lane4 << 1);
                const float bb0 = __ldg(bp + nc),     bb1 = __ldg(bp + nc + 1);
                const float bb2 = __ldg(bp + nc + 2), bb3 = __ldg(bp + nc + 3);
                const int ch = nc >> 2;
#pragma unroll
                for (int rh = 0; rh < 2; ++rh) {
                    float v0 = acc[mt][jn][rh * 2 + 0];
                    float v1 = acc[mt][jn][rh * 2 + 1];
                    float p0 = __shfl_xor_sync(0xffffffffu, v0, 1);
                    float p1 = __shfl_xor_sync(0xffffffffu, v1, 1);
                    if (!(lane & 1)) {
                        const float zi = v0 + bb0, zf = v1 + bb1, zo = p0 + bb2, zg = p1 + bb3;
                        const float gi = 1.0f / (1.0f + expf(-zi));
                        const float gf = 1.0f / (1.0f + expf(-zf));
                        const float go = 1.0f / (1.0f + expf(-zo));
                        const float gg = tanhf(zg);
                        const int pixm = pix0 + (mt << 4) + (lane >> 2) + (rh << 3);
                        const int sidx = (((b << 7) + ch) << 10) + pixm;
                        const float cn = gf * c_st[sidx] + gi * gg;
                        c_st[sidx] = cn;
                        const float hn = go * tanhf(cn);
                        const __half hr = __float2half_rn(hn);
                        const int py = (pixm >> 5) + 1, pxx = (pixm & 31) + 1;
                        const size_t ppos = (size_t)((b * 34 + py) * 34 + pxx);
                        if (LAYER == 1) {
                            g_pad1[(size_t)(par ^ 1) * P1P + ppos * C1 + 256 + ch] = hr;
                            g_pad2[(size_t)par * P2P + ppos * C23 + ch] = hr;
                        } else if (LAYER == 2) {
                            g_pad2[(size_t)(par ^ 1) * P2P + ppos * C23 + 128 + ch] = hr;
                            g_pad3[(size_t)par * P2P + ppos * C23 + ch] = hr;
                        } else {
                            g_pad3[(size_t)(par ^ 1) * P2P + ppos * C23 + 128 + ch] = hr;
                            h_out[sidx] = hn;
                        }
                    }
                }
            }
        }
    }
}

// ---------------- launch ----------------
extern "C" void kernel_launch(void* const* d_in, const int* in_sizes, int n_in,
                              void* d_out, int out_size) {
    const float* x1 = (const float*)d_in[0];
    const float* x2 = (const float*)d_in[1];
    const float* W1 = (const float*)d_in[2];
    const float* b1 = (const float*)d_in[3];
    const float* W2 = (const float*)d_in[4];
    const float* b2 = (const float*)d_in[5];
    const float* W3 = (const float*)d_in[6];
    const float* b3 = (const float*)d_in[7];
    float* out = (float*)d_out;

    float *p_c1, *p_c2, *p_c3, *p_bp1, *p_bp2, *p_bp3;
    __half *p_wf1, *p_wf2, *p_wf3;
    cudaGetSymbolAddress((void**)&p_c1, g_c1);
    cudaGetSymbolAddress((void**)&p_c2, g_c2);
    cudaGetSymbolAddress((void**)&p_c3, g_c3);
    cudaGetSymbolAddress((void**)&p_wf1, g_wf1);
    cudaGetSymbolAddress((void**)&p_wf2, g_wf2);
    cudaGetSymbolAddress((void**)&p_wf3, g_wf3);
    cudaGetSymbolAddress((void**)&p_bp1, g_bp1);
    cudaGetSymbolAddress((void**)&p_bp2, g_bp2);
    cudaGetSymbolAddress((void**)&p_bp3, g_bp3);

    cudaFuncSetAttribute(gemm_lstm_kernel<C1, 1>,
                         cudaFuncAttributeMaxDynamicSharedMemorySize, SMEM_DYN);
    cudaFuncSetAttribute(gemm_lstm_kernel<C23, 2>,
                         cudaFuncAttributeMaxDynamicSharedMemorySize, SMEM_DYN);
    cudaFuncSetAttribute(gemm_lstm_kernel<C23, 3>,
                         cudaFuncAttributeMaxDynamicSharedMemorySize, SMEM_DYN);

    const dim3 ggrid(128, 4);
    const int initBlocks = (int)((INIT_TOTAL + 255) / 256);

    init_kernel<<<initBlocks, 256>>>();
    wprep_kernel<<<(K1 * 512 + 255) / 256, 256>>>(W1, b1, W2, b2, W3, b3);

    for (int t = 0; t < TT; ++t) {
        const int par = t & 1;
        pack_x_kernel<<<128, 256>>>(x1, x2, t, par);
        gemm_lstm_kernel<C1, 1><<<ggrid, 256, SMEM_DYN>>>(p_wf1, p_bp1, p_c1, nullptr, par);
        gemm_lstm_kernel<C23, 2><<<ggrid, 256, SMEM_DYN>>>(p_wf2, p_bp2, p_c2, nullptr, par);
        gemm_lstm_kernel<C23, 3><<<ggrid, 256, SMEM_DYN>>>(p_wf3, p_bp3, p_c3, out, par);
    }
}

// round 13
// speedup vs baseline: 1.2151x; 1.2151x over previous
#include <cuda_runtime.h>
#include <cuda_fp16.h>
#include <cstdint>
#include <math.h>

// ---------------- problem constants ----------------
#define NF     128
#define BATCH  4
#define TT     8
#define NPIX   1024
#define C1     384
#define C23    256
#define K1     (C1 * 9)       // 3456
#define PADPL  (34 * 34)

// pad sizes (halves)
#define P1P (BATCH * PADPL * C1)
#define P2P (BATCH * PADPL * C23)

// GEMM tiling: CTA 64x128x32, 8 warps (2m x 4n), warp tile 32x32, mma m16n8k16
#define BM 64
#define STAGES 4
#define A_BYTES (64 * 40 * 2)       // 5120  (64 m-rows, stride 40 halves: conflict-free)
#define B_BYTES (4096 * 2)          // 8192  (128 n x 32 k halves)
#define STG_B  (A_BYTES + B_BYTES)  // 13312
#define SMEM_DYN (STAGES * STG_B)   // 53248 B -> 2 CTAs/SM

// ---------------- persistent device scratch ----------------
__device__ __align__(256) __half g_pad1[2 * P1P];   // [par][b][y][x][384]: x1|x2|h1
__device__ __align__(256) __half g_pad2[2 * P2P];   // [par][b][y][x][256]: h1|h2
__device__ __align__(256) __half g_pad3[2 * P2P];   // [par][b][y][x][256]: h2|h3
__device__ __align__(256) float g_c1[BATCH * NF * NPIX];
__device__ __align__(256) float g_c2[BATCH * NF * NPIX];
__device__ __align__(256) float g_c3[BATCH * NF * NPIX];
__device__ __align__(256) __half g_wf1[K1 * 512];
__device__ __align__(256) __half g_wf2[C23 * 9 * 512];
__device__ __align__(256) __half g_wf3[C23 * 9 * 512];
__device__ float g_bp1[512];
__device__ float g_bp2[512];
__device__ float g_bp3[512];

__device__ __forceinline__ uint32_t smem_u32(const void* p) {
    uint32_t a;
    asm("{ .reg .u64 t; cvta.to.shared.u64 t, %1; cvt.u32.u64 %0, t; }" : "=r"(a) : "l"(p));
    return a;
}
#define CP_ASYNC16(dst, src) \
    asm volatile("cp.async.cg.shared.global [%0], [%1], 16;" :: "r"(dst), "l"(src))
#define CP_COMMIT() asm volatile("cp.async.commit_group;" ::: "memory")
#define CP_WAIT(n)  asm volatile("cp.async.wait_group %0;" :: "n"(n) : "memory")

__device__ __forceinline__ void ldmatrix4(uint32_t* a, uint32_t addr) {
    asm volatile("ldmatrix.sync.aligned.m8n8.x4.shared.b16 {%0,%1,%2,%3}, [%4];"
                 : "=r"(a[0]), "=r"(a[1]), "=r"(a[2]), "=r"(a[3]) : "r"(addr));
}
__device__ __forceinline__ void lds128(uint4& v, uint32_t addr) {
    asm volatile("ld.shared.v4.b32 {%0,%1,%2,%3}, [%4];"
                 : "=r"(v.x), "=r"(v.y), "=r"(v.z), "=r"(v.w) : "r"(addr));
}
__device__ __forceinline__ void mma16(float* c, const uint32_t* a, uint32_t b0, uint32_t b1) {
    asm volatile(
        "mma.sync.aligned.m16n8k16.row.col.f32.f16.f16.f32 "
        "{%0,%1,%2,%3}, {%4,%5,%6,%7}, {%8,%9}, {%0,%1,%2,%3};"
        : "+f"(c[0]), "+f"(c[1]), "+f"(c[2]), "+f"(c[3])
        : "r"(a[0]), "r"(a[1]), "r"(a[2]), "r"(a[3]), "r"(b0), "r"(b1));
}

// ---------------- init: zero pads + c-states (1 launch) ----------------
__global__ void init_kernel() {
    long i = (long)blockIdx.x * 256 + threadIdx.x;
    long n;
    n = P1P;                 if (i < n) { ((uint32_t*)g_pad1)[i] = 0u; return; } i -= n;
    n = P2P;                 if (i < n) { ((uint32_t*)g_pad2)[i] = 0u; return; } i -= n;
    n = P2P;                 if (i < n) { ((uint32_t*)g_pad3)[i] = 0u; return; } i -= n;
    n = BATCH * NF * NPIX;
    if (i < n) { g_c1[i] = 0.0f; return; } i -= n;
    if (i < n) { g_c2[i] = 0.0f; return; } i -= n;
    if (i < n) { g_c3[i] = 0.0f; return; }
}
#define INIT_TOTAL ((long)P1P + 2L * P2P + 3L * BATCH * NF * NPIX)

// ---------------- weight prep: fp16 fragment-ordered gmem ----------------
// chunk = 32k x 128n' = 4096 halves: [ny4][ck][wn4][ks2][pair2][lane32][jj2][bsel2][h2]
__device__ __forceinline__ void wstore(const float* __restrict__ W, __half* __restrict__ out,
                                       int np, int k, int Cin, int NCH) {
    int K = Cin * 9;
    int ch = np >> 2, g = np & 3;
    int tap = k / Cin, ci = k - tap * Cin;
    __half v = __float2half_rn(W[(size_t)(g * 128 + ch) * K + ci * 9 + tap]);
    int ny = np >> 7, n_t = np & 127;
    int wn = n_t >> 5, nl = n_t & 31;
    int j = nl >> 3, rn = nl & 7, pair = j >> 1, jj = j & 1;
    int ck = k >> 5, kl = k & 31, ks = kl >> 4, rk = kl & 15;
    int bsel = rk >> 3, c = (rk & 7) >> 1, hh = rk & 1;
    int lane = rn * 4 + c;
    size_t off = (size_t)(ny * NCH + ck) * 4096 + wn * 1024 + ks * 512
               + pair * 256 + lane * 8 + jj * 4 + bsel * 2 + hh;
    out[off] = v;
}
__global__ void wprep_kernel(const float* __restrict__ W1, const float* __restrict__ b1,
                             const float* __restrict__ W2, const float* __restrict__ b2,
                             const float* __restrict__ W3, const float* __restrict__ b3) {
    int idx = blockIdx.x * 256 + threadIdx.x;
    if (idx < 512) {
        int src = (idx & 3) * 128 + (idx >> 2);
        g_bp1[idx] = b1[src]; g_bp2[idx] = b2[src]; g_bp3[idx] = b3[src];
    }
    if (idx >= K1 * 512) return;
    int np = idx & 511, k = idx >> 9;
    wstore(W1, g_wf1, np, k, C1, K1 / 32);
    if (k < C23 * 9) {
        wstore(W2, g_wf2, np, k, C23, C23 * 9 / 32);
        wstore(W3, g_wf3, np, k, C23, C23 * 9 / 32);
    }
}

// ---------------- per-step x pack: channel-last transpose (8 launches) ------
__global__ void pack_x_kernel(const float* __restrict__ x1, const float* __restrict__ x2,
                              int t, int par) {
    __shared__ __half tile[8][32][33];
    const int w = threadIdx.x >> 5, lane = threadIdx.x & 31;
    const int tl = blockIdx.x * 8 + w;
    const int b = tl >> 8, rest = tl & 255;
    const int cb = rest >> 5, pb = rest & 31;
    const int ch0 = cb * 32, pix0 = pb * 32;

    const float* src = (ch0 < 128) ? (x1 + ((size_t)(b * TT + t) * 128 + ch0) * NPIX)
                                   : (x2 + ((size_t)(b * TT + t) * 128 + ch0 - 128) * NPIX);
#pragma unroll
    for (int r = 0; r < 32; ++r)
        tile[w][r][lane] = __float2half_rn(src[(size_t)r * NPIX + pix0 + lane]);
    __syncwarp();

    __half* dst0 = g_pad1 + (size_t)par * P1P;
#pragma unroll
    for (int p = 0; p < 32; p += 2) {
        const int pp = p + (lane >> 4), ll = lane & 15;
        const int pix = pix0 + pp;
        const int py = (pix >> 5) + 1, px = (pix & 31) + 1;
        uint32_t v = ((uint32_t)__half_as_ushort(tile[w][2 * ll + 1][pp]) << 16)
                   | (uint32_t)__half_as_ushort(tile[w][2 * ll][pp]);
        __half* d = dst0 + ((size_t)((b * 34 + py) * 34 + px)) * C1 + ch0 + 2 * ll;
        *(uint32_t*)d = v;
    }
}

// ---------------- fused fp16 GEMM + LSTM kernel ----------------
// grid (64, 4), 256 threads (8 warps, 2m x 4n, warp tile 32x32), mma m16n8k16.
// Main loop unrolled by STAGES=4 (NCH % 4 == 0) -> compile-time stage offsets.
template <int C, int LAYER>
__global__ void __launch_bounds__(256, 2)
gemm_lstm_kernel(const __half* __restrict__ Bf, const float* __restrict__ bp,
                 float* __restrict__ c_st, float* __restrict__ h_out, int par)
{
    constexpr int NCH = C * 9 / 32;
    static_assert(NCH % STAGES == 0, "NCH must divide by STAGES");
    extern __shared__ char sm[];
    const uint32_t sb = smem_u32(sm);

    const int tid = threadIdx.x, w = tid >> 5, lane = tid & 31;
    const int wm = w >> 2, wn = w & 3;
    const int m0 = blockIdx.x * BM, b = m0 >> 10, pix0 = m0 & 1023;
    const int ny = blockIdx.y;
    const __half* Bny = Bf + (size_t)ny * NCH * 4096;

    // A loader: thread -> pixel px (0..63), ch-quarter chq (0,8,16,24)
    const int pxA = tid >> 2;
    const int chq = (tid & 3) << 3;
    const int pixL = pix0 + pxA;
    const int yL = pixL >> 5, xL = pixL & 31;

    const __half* padIn =
        (LAYER == 1) ? (g_pad1 + (size_t)par * P1P)
      : (LAYER == 2) ? (g_pad2 + (size_t)par * P2P)
                     : (g_pad3 + (size_t)par * P2P);

    // ldmatrix lane geometry
    const int q = lane >> 3, r = lane & 7;
    const uint32_t arow2 = ((wm * 32 + (q & 1) * 8 + r) * 40 + (q >> 1) * 8) * 2;
    const uint32_t bbase = (uint32_t)((wn << 11) + lane * 16);   // bytes within stage-B

    float acc[2][4][4];
#pragma unroll
    for (int mt = 0; mt < 2; ++mt)
#pragma unroll
        for (int jn = 0; jn < 4; ++jn)
#pragma unroll
            for (int qq = 0; qq < 4; ++qq) acc[mt][jn][qq] = 0.0f;

    auto issue = [&](int ck, uint32_t stA) {
        const uint32_t stB = stA + A_BYTES;
        const int kg = ck << 5;
        const int tap = kg / C;                 // compile-time divisor
        const int ch0 = kg - tap * C;
        const int kh = tap / 3, kw = tap - kh * 3;
        const __half* srcA = padIn
            + ((size_t)((b * 34 + yL + kh) * 34 + xL + kw)) * C + ch0 + chq;
        CP_ASYNC16(stA + (pxA * 40 + chq) * 2, srcA);
        const __half* srcB = Bny + ((size_t)ck << 12) + (tid << 3);
        CP_ASYNC16(stB + tid * 16, srcB);
        CP_ASYNC16(stB + 4096 + tid * 16, srcB + 2048);
        CP_COMMIT();
    };

#pragma unroll
    for (int s = 0; s < STAGES - 1; ++s) issue(s, sb + s * STG_B);

    for (int ck0 = 0; ck0 < NCH; ck0 += STAGES) {
#pragma unroll
        for (int s = 0; s < STAGES; ++s) {
            const int ck = ck0 + s;
            CP_WAIT(STAGES - 2);
            __syncthreads();
            const int nx = ck + STAGES - 1;
            if (nx < NCH)
                issue(nx, sb + (((unsigned)(s + STAGES - 1)) & (STAGES - 1)) * STG_B);

            const uint32_t As = sb + s * STG_B;                      // constant offset
            const uint32_t Bs = As + A_BYTES + bbase;

            // ---- batch ALL fragment loads (MLP), then all 16 MMAs ----
            uint32_t af[2][2][4];                                    // [ks][mt][4]
            uint4 bq[2][2];                                          // [ks][pair]
#pragma unroll
            for (int ks = 0; ks < 2; ++ks) {
#pragma unroll
                for (int mt = 0; mt < 2; ++mt)
                    ldmatrix4(af[ks][mt], As + arow2 + (mt * 640 + ks * 16) * 2);
#pragma unroll
                for (int pair = 0; pair < 2; ++pair)
                    lds128(bq[ks][pair], Bs + (ks * 512 + pair * 256) * 2);
            }
#pragma unroll
            for (int ks = 0; ks < 2; ++ks)
#pragma unroll
                for (int pair = 0; pair < 2; ++pair)
#pragma unroll
                    for (int mt = 0; mt < 2; ++mt) {
                        mma16(acc[mt][pair * 2 + 0], af[ks][mt], bq[ks][pair].x, bq[ks][pair].y);
                        mma16(acc[mt][pair * 2 + 1], af[ks][mt], bq[ks][pair].z, bq[ks][pair].w);
                    }
        }
    }

    // ---- fused LSTM epilogue + channel-last pad writes ----
    const int lane4 = lane & 3;
#pragma unroll
    for (int mt = 0; mt < 2; ++mt) {
#pragma unroll
        for (int jn = 0; jn < 4; ++jn) {
            const int nc = (ny << 7) + (wn << 5) + (jn << 3) + (lane4 << 1);
            const float bb0 = __ldg(bp + nc),     bb1 = __ldg(bp + nc + 1);
            const float bb2 = __ldg(bp + nc + 2), bb3 = __ldg(bp + nc + 3);
            const int ch = nc >> 2;
#pragma unroll
            for (int rh = 0; rh < 2; ++rh) {
                float v0 = acc[mt][jn][rh * 2 + 0];
                float v1 = acc[mt][jn][rh * 2 + 1];
                float p0 = __shfl_xor_sync(0xffffffffu, v0, 1);
                float p1 = __shfl_xor_sync(0xffffffffu, v1, 1);
                if (!(lane & 1)) {
                    const float zi = v0 + bb0, zf = v1 + bb1, zo = p0 + bb2, zg = p1 + bb3;
                    const float gi = 1.0f / (1.0f + expf(-zi));
                    const float gf = 1.0f / (1.0f + expf(-zf));
                    const float go = 1.0f / (1.0f + expf(-zo));
                    const float gg = tanhf(zg);
                    const int pixm = pix0 + (wm << 5) + (mt << 4) + (lane >> 2) + (rh << 3);
                    const int sidx = (((b << 7) + ch) << 10) + pixm;
                    const float cn = gf * c_st[sidx] + gi * gg;
                    c_st[sidx] = cn;
                    const float hn = go * tanhf(cn);
                    const __half hr = __float2half_rn(hn);
                    const int py = (pixm >> 5) + 1, pxx = (pixm & 31) + 1;
                    const size_t ppos = (size_t)((b * 34 + py) * 34 + pxx);
                    if (LAYER == 1) {
                        g_pad1[(size_t)(par ^ 1) * P1P + ppos * C1 + 256 + ch] = hr;
                        g_pad2[(size_t)par * P2P + ppos * C23 + ch] = hr;
                    } else if (LAYER == 2) {
                        g_pad2[(size_t)(par ^ 1) * P2P + ppos * C23 + 128 + ch] = hr;
                        g_pad3[(size_t)par * P2P + ppos * C23 + ch] = hr;
                    } else {
                        g_pad3[(size_t)(par ^ 1) * P2P + ppos * C23 + 128 + ch] = hr;
                        h_out[sidx] = hn;
                    }
                }
            }
        }
    }
}

// ---------------- launch ----------------
extern "C" void kernel_launch(void* const* d_in, const int* in_sizes, int n_in,
                              void* d_out, int out_size) {
    const float* x1 = (const float*)d_in[0];
    const float* x2 = (const float*)d_in[1];
    const float* W1 = (const float*)d_in[2];
    const float* b1 = (const float*)d_in[3];
    const float* W2 = (const float*)d_in[4];
    const float* b2 = (const float*)d_in[5];
    const float* W3 = (const float*)d_in[6];
    const float* b3 = (const float*)d_in[7];
    float* out = (float*)d_out;

    float *p_c1, *p_c2, *p_c3, *p_bp1, *p_bp2, *p_bp3;
    __half *p_wf1, *p_wf2, *p_wf3;
    cudaGetSymbolAddress((void**)&p_c1, g_c1);
    cudaGetSymbolAddress((void**)&p_c2, g_c2);
    cudaGetSymbolAddress((void**)&p_c3, g_c3);
    cudaGetSymbolAddress((void**)&p_wf1, g_wf1);
    cudaGetSymbolAddress((void**)&p_wf2, g_wf2);
    cudaGetSymbolAddress((void**)&p_wf3, g_wf3);
    cudaGetSymbolAddress((void**)&p_bp1, g_bp1);
    cudaGetSymbolAddress((void**)&p_bp2, g_bp2);
    cudaGetSymbolAddress((void**)&p_bp3, g_bp3);

    cudaFuncSetAttribute(gemm_lstm_kernel<C1, 1>,
                         cudaFuncAttributeMaxDynamicSharedMemorySize, SMEM_DYN);
    cudaFuncSetAttribute(gemm_lstm_kernel<C23, 2>,
                         cudaFuncAttributeMaxDynamicSharedMemorySize, SMEM_DYN);
    cudaFuncSetAttribute(gemm_lstm_kernel<C23, 3>,
                         cudaFuncAttributeMaxDynamicSharedMemorySize, SMEM_DYN);

    const dim3 ggrid(64, 4);
    const int initBlocks = (int)((INIT_TOTAL + 255) / 256);

    init_kernel<<<initBlocks, 256>>>();
    wprep_kernel<<<(K1 * 512 + 255) / 256, 256>>>(W1, b1, W2, b2, W3, b3);

    for (int t = 0; t < TT; ++t) {
        const int par = t & 1;
        pack_x_kernel<<<128, 256>>>(x1, x2, t, par);
        gemm_lstm_kernel<C1, 1><<<ggrid, 256, SMEM_DYN>>>(p_wf1, p_bp1, p_c1, nullptr, par);
        gemm_lstm_kernel<C23, 2><<<ggrid, 256, SMEM_DYN>>>(p_wf2, p_bp2, p_c2, nullptr, par);
        gemm_lstm_kernel<C23, 3><<<ggrid, 256, SMEM_DYN>>>(p_wf3, p_bp3, p_c3, out, par);
    }
}